// round 11
// baseline (speedup 1.0000x reference)
#include <cuda_runtime.h>

// CWT: out[b,i,n] = Re{ sum_{k=0}^{4} w[k] * signal[b, n - wl_i + k] }
// w[k] = exp(-0.5 k^2) * exp(j*2pi*k/6), nrm=1. |w[5]|~1.9e-6 -> K=5 gives
// rel_err ~1.8e-6 (measured) vs threshold 1e-3.
// Output buffer = float32 real part (out_size == 524288, confirmed R5-R10).
// Kernel is at the launch-overhead floor (~4.5us regardless of inner work);
// this round A/Bs launch geometry: 512 CTAs x 512 threads (was 1024x256),
// branchless boundary handling.

#define CWT_NSCALES 32
#define CWT_L       4096
#define CWT_B       4
#define CWT_K       5
#define CWT_V       2
#define CWT_TPB     512

__constant__ int c_wl[CWT_NSCALES] = {
      64,  194,  324,  454,  584,  714,  844,  974,
    1104, 1234, 1364, 1494, 1624, 1754, 1884, 2014,
    2048, 2048, 2048, 2048, 2048, 2048, 2048, 2048,
    2048, 2048, 2048, 2048, 2048, 2048, 2048, 2048
};

// w_re[k] = exp(-0.5 k^2) * cos(2 pi k / 6)
__device__ __constant__ float c_wr[CWT_K] = {
    1.0f,                   0.3032653298563167f,   -0.06766764161830635f,
   -0.011108996538242306f, -1.6773131395125593e-4f
};
// w_im[k] (fallback interleaved mode only)
__device__ __constant__ float c_wi[CWT_K] = {
    0.0f,                   0.5252752119703823f,     0.11720384084196092f,
    0.0f,                  -2.9051333293715680e-4f
};

template <int MODE>  // 0: real-only floats; 1: interleaved re/im floats
__global__ void __launch_bounds__(CWT_TPB)
cwt81003_kernel(const float* __restrict__ sig, float* __restrict__ out)
{
    const int t   = blockIdx.x * CWT_TPB + threadIdx.x;  // 0 .. 262143
    const int row = t >> 11;                  // (b*32+i); 2048 threads per row
    const int n0  = (t & 2047) * CWT_V;       // even
    const int i   = row & (CWT_NSCALES - 1);
    const int b   = row >> 5;

    const int wl   = c_wl[i];
    const int base = n0 - wl;                 // even

    float r0 = 0.0f, r1 = 0.0f;
    float i0 = 0.0f, i1 = 0.0f;

    if (base >= 0) {
        // Fast path (vast majority): 3 aligned float2 loads, 6 samples.
        const float2* p2 = (const float2*)(sig + b * CWT_L + base);
        float2 a = __ldg(p2 + 0);
        float2 c = __ldg(p2 + 1);
        float2 d = __ldg(p2 + 2);
        float x0 = a.x, x1 = a.y, x2 = c.x, x3 = c.y, x4 = d.x, x5 = d.y;
        r0 = fmaf(c_wr[0], x0, fmaf(c_wr[1], x1, fmaf(c_wr[2], x2,
             fmaf(c_wr[3], x3, c_wr[4] * x4))));
        r1 = fmaf(c_wr[0], x1, fmaf(c_wr[1], x2, fmaf(c_wr[2], x3,
             fmaf(c_wr[3], x4, c_wr[4] * x5))));
        if (MODE == 1) {
            i0 = fmaf(c_wi[1], x1, fmaf(c_wi[2], x2, c_wi[4] * x4));
            i1 = fmaf(c_wi[1], x2, fmaf(c_wi[2], x3, c_wi[4] * x5));
        }
    } else if (base + CWT_V + CWT_K - 2 >= 0) {
        // Boundary (one 2-output window per row): branchless clamped loads.
        const float* p = sig + b * CWT_L;
        #pragma unroll
        for (int k = 0; k < CWT_K; k++) {
            int g0 = base + k;
            float x0 = (g0     >= 0) ? __ldg(p + g0)     : 0.0f;
            float x1 = (g0 + 1 >= 0) ? __ldg(p + g0 + 1) : 0.0f;
            r0 = fmaf(c_wr[k], x0, r0);
            r1 = fmaf(c_wr[k], x1, r1);
            if (MODE == 1) {
                i0 = fmaf(c_wi[k], x0, i0);
                i1 = fmaf(c_wi[k], x1, i1);
            }
        }
    }
    // else: window entirely left of signal -> zeros.

    if (MODE == 0) {
        *(float2*)(out + (long)row * CWT_L + n0) = make_float2(r0, r1);
    } else {
        *(float4*)(out + 2 * ((long)row * CWT_L + n0)) = make_float4(r0, i0, r1, i1);
    }
}

extern "C" void kernel_launch(void* const* d_in, const int* in_sizes, int n_in,
                              void* d_out, int out_size)
{
    const float* sig = (const float*)d_in[0];
    float* out = (float*)d_out;

    const long logical = (long)CWT_B * CWT_NSCALES * CWT_L;   // 524288 outputs
    const int nblocks  = (int)(logical / CWT_V / CWT_TPB);    // 512

    if ((long)out_size >= 2 * logical)
        cwt81003_kernel<1><<<nblocks, CWT_TPB>>>(sig, out);
    else
        cwt81003_kernel<0><<<nblocks, CWT_TPB>>>(sig, out);
}

// round 12
// speedup vs baseline: 1.0337x; 1.0337x over previous
#include <cuda_runtime.h>

// CWT: out[b,i,n] = Re{ sum_{k=0}^{4} w[k] * signal[b, n - wl_i + k] }
// w[k] = exp(-0.5 k^2) * exp(j*2pi*k/6), nrm=1. |w[5]|~1.9e-6 -> K=5 gives
// rel_err ~1.8e-6 (measured) vs threshold 1e-3.
// Output buffer = float32 real part (out_size == 524288, confirmed R5-R11).
//
// Converged configuration (measured best across R5-R11): flat 1D grid,
// 1024 CTAs x 256 threads, V=2 outputs/thread, 3 aligned LDG.64 + 10 FFMA +
// 1 STG.64. Kernel sits at the GB300 launch/ramp floor (~4.5us): all pipes
// <5% busy; further inner-loop reduction is unmeasurable.

#define CWT_NSCALES 32
#define CWT_L       4096
#define CWT_B       4
#define CWT_K       5
#define CWT_V       2
#define CWT_TPB     256

__constant__ int c_wl[CWT_NSCALES] = {
      64,  194,  324,  454,  584,  714,  844,  974,
    1104, 1234, 1364, 1494, 1624, 1754, 1884, 2014,
    2048, 2048, 2048, 2048, 2048, 2048, 2048, 2048,
    2048, 2048, 2048, 2048, 2048, 2048, 2048, 2048
};

// w_re[k] = exp(-0.5 k^2) * cos(2 pi k / 6)
__device__ __constant__ float c_wr[CWT_K] = {
    1.0f,                   0.3032653298563167f,   -0.06766764161830635f,
   -0.011108996538242306f, -1.6773131395125593e-4f
};
// w_im[k] (fallback interleaved mode only)
__device__ __constant__ float c_wi[CWT_K] = {
    0.0f,                   0.5252752119703823f,     0.11720384084196092f,
    0.0f,                  -2.9051333293715680e-4f
};

template <int MODE>  // 0: real-only floats; 1: interleaved re/im floats
__global__ void __launch_bounds__(CWT_TPB)
cwt81003_kernel(const float* __restrict__ sig, float* __restrict__ out)
{
    const int t   = blockIdx.x * CWT_TPB + threadIdx.x;  // 0 .. 262143
    const int row = t >> 11;                  // (b*32+i); 2048 threads per row
    const int n0  = (t & 2047) * CWT_V;       // even
    const int i   = row & (CWT_NSCALES - 1);
    const int b   = row >> 5;

    const int wl   = c_wl[i];
    const int base = n0 - wl;                 // even

    float r0 = 0.0f, r1 = 0.0f;
    float i0 = 0.0f, i1 = 0.0f;

    if (base >= 0) {
        // Fast path: 3 aligned float2 loads, balanced FMA trees.
        const float2* p2 = (const float2*)(sig + b * CWT_L + base);
        const float2 a = __ldg(p2 + 0);
        const float2 c = __ldg(p2 + 1);
        const float2 d = __ldg(p2 + 2);
        // r0 over {a.x,a.y,c.x,c.y,d.x}; r1 over {a.y,c.x,c.y,d.x,d.y}
        float t0 = fmaf(c_wr[1], a.y, c_wr[0] * a.x);
        float t1 = fmaf(c_wr[3], c.y, c_wr[2] * c.x);
        r0 = fmaf(c_wr[4], d.x, t0 + t1);
        float u0 = fmaf(c_wr[1], c.x, c_wr[0] * a.y);
        float u1 = fmaf(c_wr[3], d.x, c_wr[2] * c.y);
        r1 = fmaf(c_wr[4], d.y, u0 + u1);
        if (MODE == 1) {
            i0 = fmaf(c_wi[1], a.y, fmaf(c_wi[2], c.x, c_wi[4] * d.x));
            i1 = fmaf(c_wi[1], c.x, fmaf(c_wi[2], c.y, c_wi[4] * d.y));
        }
    } else if (base + CWT_V + CWT_K - 2 >= 0) {
        // Boundary: at most one window per (b,i) row reaches here.
        const float* p = sig + b * CWT_L;
        #pragma unroll
        for (int k = 0; k < CWT_K; k++) {
            int g = base + k;
            float x0 = (g     >= 0) ? __ldg(p + g)     : 0.0f;
            float x1 = (g + 1 >= 0) ? __ldg(p + g + 1) : 0.0f;
            r0 = fmaf(c_wr[k], x0, r0);
            r1 = fmaf(c_wr[k], x1, r1);
            if (MODE == 1) {
                i0 = fmaf(c_wi[k], x0, i0);
                i1 = fmaf(c_wi[k], x1, i1);
            }
        }
    }
    // else: window entirely left of signal -> zeros.

    if (MODE == 0) {
        *(float2*)(out + (long)row * CWT_L + n0) = make_float2(r0, r1);
    } else {
        *(float4*)(out + 2 * ((long)row * CWT_L + n0)) = make_float4(r0, i0, r1, i1);
    }
}

extern "C" void kernel_launch(void* const* d_in, const int* in_sizes, int n_in,
                              void* d_out, int out_size)
{
    const float* sig = (const float*)d_in[0];
    float* out = (float*)d_out;

    const long logical = (long)CWT_B * CWT_NSCALES * CWT_L;   // 524288 outputs
    const int nblocks  = (int)(logical / CWT_V / CWT_TPB);    // 1024

    if ((long)out_size >= 2 * logical)
        cwt81003_kernel<1><<<nblocks, CWT_TPB>>>(sig, out);
    else
        cwt81003_kernel<0><<<nblocks, CWT_TPB>>>(sig, out);
}

// round 13
// speedup vs baseline: 1.0750x; 1.0400x over previous
#include <cuda_runtime.h>

// CWT: out[b,i,n] = Re{ sum_{k=0}^{7} w[k] * signal[b, n - wl_i + k] }
// w[k] = exp(-0.5 k^2) * exp(j*2pi*k/6), nrm = 1; envelope < 1.3e-14 past k=7,
// so K=8 (here: K=6 active taps, k=6,7 dropped at <1.6e-8) reproduces the full
// reference convolution to rel_err ~4.8e-8 (measured, threshold 1e-3).
// Output buffer = float32 real part (out_size == 524288, confirmed R5-R12).
//
// FINAL (converged R5-R12): flat 1D grid, 1024 CTAs x 256 threads, V=2
// outputs/thread, 4 aligned LDG.64 + 12 FFMA + 1 STG.64. Kernel sits at the
// GB300 launch/ramp floor (~4.6us measured): all pipes <5% busy; equal-best
// ncu time and best dur_us of all configurations tested.

#define CWT_NSCALES 32
#define CWT_L       4096
#define CWT_B       4
#define CWT_K       6
#define CWT_V       2
#define CWT_TPB     256

__constant__ int c_wl[CWT_NSCALES] = {
      64,  194,  324,  454,  584,  714,  844,  974,
    1104, 1234, 1364, 1494, 1624, 1754, 1884, 2014,
    2048, 2048, 2048, 2048, 2048, 2048, 2048, 2048,
    2048, 2048, 2048, 2048, 2048, 2048, 2048, 2048
};

// w_re[k] = exp(-0.5 k^2) * cos(2 pi k / 6)
__device__ __constant__ float c_wr[CWT_K] = {
    1.0f,                   0.3032653298563167f,   -0.06766764161830635f,
   -0.011108996538242306f, -1.6773131395125593e-4f, 1.8633265860393355e-6f
};
// w_im[k] (fallback interleaved mode only)
__device__ __constant__ float c_wi[CWT_K] = {
    0.0f,                   0.5252752119703823f,     0.11720384084196092f,
    0.0f,                  -2.9051333293715680e-4f, -3.2275577425105797e-6f
};

template <int MODE>  // 0: real-only floats; 1: interleaved re/im floats
__global__ void __launch_bounds__(CWT_TPB)
cwt81003_kernel(const float* __restrict__ sig, float* __restrict__ out)
{
    const int t   = blockIdx.x * CWT_TPB + threadIdx.x;  // 0 .. 262143
    const int row = t >> 11;                  // (b*32+i); 2048 threads per row
    const int n0  = (t & 2047) * CWT_V;       // even
    const int i   = row & (CWT_NSCALES - 1);
    const int b   = row >> 5;

    const int wl   = c_wl[i];
    const int base = n0 - wl;                 // even

    float r0 = 0.0f, r1 = 0.0f;
    float i0 = 0.0f, i1 = 0.0f;

    if (n0 + CWT_V + CWT_K - 2 >= wl) {       // window touches the signal
        float x[CWT_V + CWT_K - 1];           // 7 samples
        const float* p = sig + b * CWT_L + base;
        if (base >= 0) {
            // base even, sig 8B-aligned -> four aligned float2 loads (8 floats, 7 used)
            const float2* p2 = (const float2*)p;
            float2 a = __ldg(p2 + 0);
            float2 c = __ldg(p2 + 1);
            float2 d = __ldg(p2 + 2);
            float2 e = __ldg(p2 + 3);
            x[0] = a.x; x[1] = a.y; x[2] = c.x; x[3] = c.y;
            x[4] = d.x; x[5] = d.y; x[6] = e.x;
        } else {
            #pragma unroll
            for (int j = 0; j < CWT_V + CWT_K - 1; j++)
                x[j] = (base + j >= 0) ? __ldg(p + j) : 0.0f;
        }
        #pragma unroll
        for (int k = 0; k < CWT_K; k++) {
            r0 = fmaf(c_wr[k], x[k],     r0);
            r1 = fmaf(c_wr[k], x[k + 1], r1);
            if (MODE == 1) {
                i0 = fmaf(c_wi[k], x[k],     i0);
                i1 = fmaf(c_wi[k], x[k + 1], i1);
            }
        }
    }

    if (MODE == 0) {
        *(float2*)(out + (long)row * CWT_L + n0) = make_float2(r0, r1);
    } else {
        *(float4*)(out + 2 * ((long)row * CWT_L + n0)) = make_float4(r0, i0, r1, i1);
    }
}

extern "C" void kernel_launch(void* const* d_in, const int* in_sizes, int n_in,
                              void* d_out, int out_size)
{
    const float* sig = (const float*)d_in[0];
    float* out = (float*)d_out;

    const long logical = (long)CWT_B * CWT_NSCALES * CWT_L;   // 524288 outputs
    const int nblocks  = (int)(logical / CWT_V / CWT_TPB);    // 1024

    if ((long)out_size >= 2 * logical)
        cwt81003_kernel<1><<<nblocks, CWT_TPB>>>(sig, out);
    else
        cwt81003_kernel<0><<<nblocks, CWT_TPB>>>(sig, out);
}

// round 14
// speedup vs baseline: 1.1082x; 1.0309x over previous
#include <cuda_runtime.h>

// CWT: out[b,i,n] = Re{ sum_{k=0}^{7} w[k] * signal[b, n - wl_i + k] }
// w[k] = exp(-0.5 k^2) * exp(j*2pi*k/6), nrm = 1; envelope < 1.3e-14 past k=7,
// so K=6 active taps (k=6,7 dropped at <1.6e-8) reproduce the full reference
// convolution to rel_err ~4.9e-8 (measured, threshold 1e-3).
// Output buffer = float32 real part (out_size == 524288, confirmed R5-R13).
//
// FINAL (converged R5-R13): flat 1D grid, 1024 CTAs x 256 threads, V=2
// outputs/thread, 4 aligned LDG.64 + 12 FFMA + 1 STG.64, 16 regs, no smem.
// Kernel sits at the GB300 launch/ramp floor: same binary measures
// 4.58-4.86us ncu / 5.57-6.40us dur across runs; all pipes <5% busy.
// Fully characterized configuration space: this shape is the measured optimum.

#define CWT_NSCALES 32
#define CWT_L       4096
#define CWT_B       4
#define CWT_K       6
#define CWT_V       2
#define CWT_TPB     256

__constant__ int c_wl[CWT_NSCALES] = {
      64,  194,  324,  454,  584,  714,  844,  974,
    1104, 1234, 1364, 1494, 1624, 1754, 1884, 2014,
    2048, 2048, 2048, 2048, 2048, 2048, 2048, 2048,
    2048, 2048, 2048, 2048, 2048, 2048, 2048, 2048
};

// w_re[k] = exp(-0.5 k^2) * cos(2 pi k / 6)
__device__ __constant__ float c_wr[CWT_K] = {
    1.0f,                   0.3032653298563167f,   -0.06766764161830635f,
   -0.011108996538242306f, -1.6773131395125593e-4f, 1.8633265860393355e-6f
};
// w_im[k] (fallback interleaved mode only)
__device__ __constant__ float c_wi[CWT_K] = {
    0.0f,                   0.5252752119703823f,     0.11720384084196092f,
    0.0f,                  -2.9051333293715680e-4f, -3.2275577425105797e-6f
};

template <int MODE>  // 0: real-only floats; 1: interleaved re/im floats
__global__ void __launch_bounds__(CWT_TPB)
cwt81003_kernel(const float* __restrict__ sig, float* __restrict__ out)
{
    const int t   = blockIdx.x * CWT_TPB + threadIdx.x;  // 0 .. 262143
    const int row = t >> 11;                  // (b*32+i); 2048 threads per row
    const int n0  = (t & 2047) * CWT_V;       // even
    const int i   = row & (CWT_NSCALES - 1);
    const int b   = row >> 5;

    const int wl   = c_wl[i];
    const int base = n0 - wl;                 // even

    float r0 = 0.0f, r1 = 0.0f;
    float i0 = 0.0f, i1 = 0.0f;

    if (n0 + CWT_V + CWT_K - 2 >= wl) {       // window touches the signal
        float x[CWT_V + CWT_K - 1];           // 7 samples
        const float* p = sig + b * CWT_L + base;
        if (base >= 0) {
            // base even, sig 8B-aligned -> four aligned float2 loads (8 floats, 7 used)
            const float2* p2 = (const float2*)p;
            float2 a = __ldg(p2 + 0);
            float2 c = __ldg(p2 + 1);
            float2 d = __ldg(p2 + 2);
            float2 e = __ldg(p2 + 3);
            x[0] = a.x; x[1] = a.y; x[2] = c.x; x[3] = c.y;
            x[4] = d.x; x[5] = d.y; x[6] = e.x;
        } else {
            #pragma unroll
            for (int j = 0; j < CWT_V + CWT_K - 1; j++)
                x[j] = (base + j >= 0) ? __ldg(p + j) : 0.0f;
        }
        #pragma unroll
        for (int k = 0; k < CWT_K; k++) {
            r0 = fmaf(c_wr[k], x[k],     r0);
            r1 = fmaf(c_wr[k], x[k + 1], r1);
            if (MODE == 1) {
                i0 = fmaf(c_wi[k], x[k],     i0);
                i1 = fmaf(c_wi[k], x[k + 1], i1);
            }
        }
    }

    if (MODE == 0) {
        *(float2*)(out + (long)row * CWT_L + n0) = make_float2(r0, r1);
    } else {
        *(float4*)(out + 2 * ((long)row * CWT_L + n0)) = make_float4(r0, i0, r1, i1);
    }
}

extern "C" void kernel_launch(void* const* d_in, const int* in_sizes, int n_in,
                              void* d_out, int out_size)
{
    const float* sig = (const float*)d_in[0];
    float* out = (float*)d_out;

    const long logical = (long)CWT_B * CWT_NSCALES * CWT_L;   // 524288 outputs
    const int nblocks  = (int)(logical / CWT_V / CWT_TPB);    // 1024

    if ((long)out_size >= 2 * logical)
        cwt81003_kernel<1><<<nblocks, CWT_TPB>>>(sig, out);
    else
        cwt81003_kernel<0><<<nblocks, CWT_TPB>>>(sig, out);
}